// round 15
// baseline (speedup 1.0000x reference)
#include <cuda_runtime.h>
#include <cuda_bf16.h>
#include <cstdint>

#define TT 256
#define BB 64
#define DD 1024
#define HH 1024
#define G4 4096
#define EPSF 0.01f
#define NCTA 128
#define NTHR 512

typedef unsigned long long ull;
typedef unsigned short u16;

// ---------------- device scratch -------------------------------------------
static __device__ float g_G[(size_t)TT * BB * G4];   // x@W_ih.T + b_ih + b_hh
static __device__ float g_xn2[TT * BB];              // |x_t|^2
static __device__ float g_hn2[(TT + 1) * BB];        // |h_t|^2 (atomics)
// A-image in mma fragment layout: [parity][kt(64)*mt(8)*lane(32)] uint4
static __device__ uint4 g_Ahi[2][16384];
static __device__ uint4 g_Alo[2][16384];
// packed fragment images for pre_gemm (bf16 hi/lo, SMEM-layout-identical)
static __device__ uint4 g_xpack[(size_t)128 * 64 * 512];  // [mb][kt][mt][lane][2]
static __device__ uint4 g_wpack[(size_t)32 * 64 * 512];   // [nb][kt][wq][lane]
static __device__ unsigned g_bar;                    // global step barrier

// ---------------- init (runs every replay) ----------------------------------
__global__ void init_kernel() {
    int idx = blockIdx.x * blockDim.x + threadIdx.x;
    int stride = gridDim.x * blockDim.x;
    uint4 z = make_uint4(0u, 0u, 0u, 0u);
    for (int i = idx; i < 16384; i += stride) {
        g_Ahi[0][i] = z;
        g_Alo[0][i] = z;
    }
    for (int i = idx; i < (TT + 1) * BB; i += stride) g_hn2[i] = 0.f;
    if (idx == 0) g_bar = 0u;
}

// ---------------- |x_t|^2 ---------------------------------------------------
__global__ void xnorm_kernel(const float* __restrict__ x) {
    int row = blockIdx.x;
    const float* xr = x + (size_t)row * DD;
    float s = 0.f;
    for (int i = threadIdx.x; i < DD; i += blockDim.x) { float v = xr[i]; s += v * v; }
    __shared__ float red[8];
    #pragma unroll
    for (int o = 16; o > 0; o >>= 1) s += __shfl_xor_sync(0xffffffffu, s, o);
    if ((threadIdx.x & 31) == 0) red[threadIdx.x >> 5] = s;
    __syncthreads();
    if (threadIdx.x < 8) {
        s = red[threadIdx.x];
        #pragma unroll
        for (int o = 4; o > 0; o >>= 1) s += __shfl_xor_sync(0xffu, s, o);
        if (threadIdx.x == 0) g_xn2[row] = s;
    }
}

// ---------------- helpers -----------------------------------------------------
__device__ __forceinline__ void mma_bf16(float* d, uint4 a, uint32_t b0, uint32_t b1) {
    asm volatile(
        "mma.sync.aligned.m16n8k16.row.col.f32.bf16.bf16.f32 "
        "{%0,%1,%2,%3}, {%4,%5,%6,%7}, {%8,%9}, {%0,%1,%2,%3};"
        : "+f"(d[0]), "+f"(d[1]), "+f"(d[2]), "+f"(d[3])
        : "r"(a.x), "r"(a.y), "r"(a.z), "r"(a.w), "r"(b0), "r"(b1));
}
__device__ __forceinline__ u16 bfu(__nv_bfloat16 b) {
    return __bfloat16_as_ushort(b);
}
__device__ __forceinline__ void split_bf(float v, u16& h, u16& l) {
    __nv_bfloat16 hb = __float2bfloat16(v);
    h = bfu(hb);
    l = bfu(__float2bfloat16(v - __bfloat162float(hb)));
}

// ---------------- prepack: x -> fragment image (bf16 hi/lo) -------------------
__global__ void prepack_x(const float* __restrict__ x) {
    const int row = blockIdx.x;          // 0..16383
    const int kq  = threadIdx.x;         // float4 index 0..255
    float4 v = __ldg((const float4*)(x + (size_t)row * DD) + kq);
    const int mb = row >> 7, r = row & 127, mt = r >> 4;
    u16* dst = (u16*)g_xpack;
    #pragma unroll
    for (int p = 0; p < 2; p++) {
        int kp = kq * 2 + p;
        int kt = kp >> 3, tigc = kp & 3, regk = (kp >> 2) & 1;
        int lane_f = (r & 7) * 4 + tigc;
        int reg = ((r >> 3) & 1) + 2 * regk;
        float v0 = p ? v.z : v.x, v1 = p ? v.w : v.y;
        u16 h0, l0, h1, l1;
        split_bf(v0, h0, l0); split_bf(v1, h1, l1);
        size_t base = ((((size_t)mb * 64 + kt) * 8 + mt) * 32 + lane_f) * 16 + reg * 2;
        *(ushort2*)&dst[base]     = make_ushort2(h0, h1);
        *(ushort2*)&dst[base + 8] = make_ushort2(l0, l1);
    }
}

// ---------------- prepack: W_ih -> fragment image (bf16 hi/lo) ----------------
__global__ void prepack_w(const float* __restrict__ Wih) {
    const int row = blockIdx.x;          // n-row 0..4095
    const int kq  = threadIdx.x;
    float4 v = __ldg((const float4*)(Wih + (size_t)row * DD) + kq);
    const int nb = row >> 7, r = row & 127, wq = r >> 3;
    u16* dst = (u16*)g_wpack;
    #pragma unroll
    for (int p = 0; p < 2; p++) {
        int kp = kq * 2 + p;
        int kt = kp >> 3, tigc = kp & 3, regk = (kp >> 2) & 1;
        int lane_f = (r & 7) * 4 + tigc;
        float v0 = p ? v.z : v.x, v1 = p ? v.w : v.y;
        u16 h0, l0, h1, l1;
        split_bf(v0, h0, l0); split_bf(v1, h1, l1);
        size_t base = ((((size_t)nb * 64 + kt) * 16 + wq) * 32 + lane_f) * 8 + regk * 2;
        *(ushort2*)&dst[base]     = make_ushort2(h0, h1);
        *(ushort2*)&dst[base + 4] = make_ushort2(l0, l1);
    }
}

// ---------------- HMMA precompute GEMM: G = x @ W_ih.T + (b_ih + b_hh) ------
#define PG_SMEM (4096 * 16)

__global__ void __launch_bounds__(256)
pre_gemm_hmma(const float* __restrict__ bih, const float* __restrict__ bhh) {
    extern __shared__ __align__(16) uint4 sv[];
    uint4* xv = sv;          // [buf][1024]
    uint4* wv = sv + 2048;   // [buf][1024]

    const int tid  = threadIdx.x;
    const int w    = tid >> 5;
    const int lane = tid & 31;
    const int gid  = lane >> 2;
    const int tig  = lane & 3;
    const int wm   = w >> 1;
    const int wn   = w & 1;
    const int nb   = blockIdx.x;
    const int mb   = blockIdx.y;
    const int n0   = nb * 128;
    const int m0   = mb * 128;

    const uint4* xg = g_xpack + (size_t)mb * 64 * 512;
    const uint4* wg = g_wpack + (size_t)nb * 64 * 512;

    float acc[2][8][4];
    #pragma unroll
    for (int i = 0; i < 2; i++)
        #pragma unroll
        for (int j = 0; j < 8; j++)
            #pragma unroll
            for (int e = 0; e < 4; e++) acc[i][j][e] = 0.f;

    uint4 st[8];
    auto LDGC = [&](int ch) {
        const uint4* xs = xg + (size_t)ch * 1024;
        const uint4* ws = wg + (size_t)ch * 1024;
        #pragma unroll
        for (int i = 0; i < 4; i++) st[i]     = __ldg(xs + tid + i * 256);
        #pragma unroll
        for (int i = 0; i < 4; i++) st[4 + i] = __ldg(ws + tid + i * 256);
    };
    auto STSC = [&](int buf) {
        #pragma unroll
        for (int i = 0; i < 4; i++) xv[buf * 1024 + tid + i * 256] = st[i];
        #pragma unroll
        for (int i = 0; i < 4; i++) wv[buf * 1024 + tid + i * 256] = st[4 + i];
    };

    LDGC(0);
    STSC(0);
    __syncthreads();

    for (int ch = 0; ch < 32; ch++) {
        const int buf = ch & 1;
        if (ch < 31) LDGC(ch + 1);
        #pragma unroll
        for (int kt = 0; kt < 2; kt++) {
            int fi0 = buf * 1024 + ((kt * 8 + wm * 2) * 32 + lane) * 2;
            uint4 ah0 = xv[fi0],      al0 = xv[fi0 + 1];
            uint4 ah1 = xv[fi0 + 64], al1 = xv[fi0 + 65];
            #pragma unroll
            for (int nf = 0; nf < 8; nf++) {
                uint4 wvv = wv[buf * 1024 + (kt * 16 + wn * 8 + nf) * 32 + lane];
                mma_bf16(acc[0][nf], ah0, wvv.x, wvv.y);
                mma_bf16(acc[0][nf], al0, wvv.x, wvv.y);
                mma_bf16(acc[0][nf], ah0, wvv.z, wvv.w);
                mma_bf16(acc[1][nf], ah1, wvv.x, wvv.y);
                mma_bf16(acc[1][nf], al1, wvv.x, wvv.y);
                mma_bf16(acc[1][nf], ah1, wvv.z, wvv.w);
            }
        }
        if (ch < 31) {
            STSC(buf ^ 1);
            __syncthreads();
        }
    }

    #pragma unroll
    for (int nf = 0; nf < 8; nf++) {
        int col = n0 + wn * 64 + nf * 8 + tig * 2;
        float bs0 = __ldg(&bih[col])     + __ldg(&bhh[col]);
        float bs1 = __ldg(&bih[col + 1]) + __ldg(&bhh[col + 1]);
        #pragma unroll
        for (int im = 0; im < 2; im++) {
            int row = m0 + wm * 32 + im * 16 + gid;
            float2 v0; v0.x = acc[im][nf][0] + bs0; v0.y = acc[im][nf][1] + bs1;
            float2 v1; v1.x = acc[im][nf][2] + bs0; v1.y = acc[im][nf][3] + bs1;
            *(float2*)&g_G[(size_t)row * G4 + col]       = v0;
            *(float2*)&g_G[(size_t)(row + 8) * G4 + col] = v1;
        }
    }
}

// ---------------- persistent HMMA recurrence kernel ---------------------------
// 16 warps; warp = (mtp = w&3 covering m-tiles 2mtp, 2mtp+1; kq = w>>2, 16 kt).
// W fragments fetched ONCE per k2 and reused across 2 A m-tiles -> W crossbar
// traffic halved. A ring: depth 2 x 2 mt x 2 planes (same 32 regs).
// SMEM: Wfrag 128KB; pre float[4 kq][128][34] = 69632B.
#define WFRAG_BYTES (256 * 32 * 16)
#define PRE_STRIDE 34
#define PRE_Q      (128 * PRE_STRIDE)
#define SMEM_TOTAL (WFRAG_BYTES + 4 * PRE_Q * 4)

__global__ void __launch_bounds__(NTHR, 1)
persist_kernel(const float* __restrict__ gp, const float* __restrict__ Whh,
               float* __restrict__ out) {
    extern __shared__ __align__(16) char sraw[];
    uint4* Wfrag = (uint4*)sraw;
    float* pre   = (float*)(sraw + WFRAG_BYTES);

    const int tid  = threadIdx.x;
    const int w    = tid >> 5;
    const int lane = tid & 31;
    const int mtp  = w & 3;
    const int kq   = w >> 2;
    const int gid  = lane >> 2;
    const int tig  = lane & 3;
    const int n0   = blockIdx.x * 8;
    const int jj   = tid & 7;
    const int b    = tid >> 3;           // 0..63 (tid < 512)

    // ---- one-time: build W fragments (hi/lo) into SMEM ----------------------
    #pragma unroll 1
    for (int idx = w; idx < 256; idx += 16) {
        int q = idx & 3, kt = idx >> 2;
        const float* wr = Whh + (size_t)(q * HH + n0 + gid) * HH + kt * 16 + tig * 2;
        float v00 = __ldg(wr), v01 = __ldg(wr + 1);
        float v10 = __ldg(wr + 8), v11 = __ldg(wr + 9);
        u16 h00, l00, h01, l01, h10, l10, h11, l11;
        split_bf(v00, h00, l00); split_bf(v01, h01, l01);
        split_bf(v10, h10, l10); split_bf(v11, h11, l11);
        Wfrag[idx * 32 + lane] = make_uint4(
            (uint32_t)h00 | ((uint32_t)h01 << 16),
            (uint32_t)h10 | ((uint32_t)h11 << 16),
            (uint32_t)l00 | ((uint32_t)l01 << 16),
            (uint32_t)l10 | ((uint32_t)l11 << 16));
    }
    __syncthreads();

    float cst = 0.f, dcst = 0.f;
    const size_t OFF = (size_t)TT * BB * HH;

    for (int t = 0; t < TT; t++) {
        // ---- HMMA mainloop: W reuse across 2 m-tiles, depth-2 ring ------------
        float acc[2][4][4];
        #pragma unroll
        for (int i = 0; i < 2; i++)
            #pragma unroll
            for (int q = 0; q < 4; q++)
                #pragma unroll
                for (int e = 0; e < 4; e++) acc[i][q][e] = 0.f;

        const uint4* Ah = g_Ahi[t & 1];
        const uint4* Al = g_Alo[t & 1];
        const int ktb = kq * 16;
        const int fb0 = (2 * mtp) * 32 + lane;
        const int fb1 = (2 * mtp + 1) * 32 + lane;

        uint4 rh[2][2], rl[2][2];
        #pragma unroll
        for (int d = 0; d < 2; d++) {
            rh[0][d] = __ldcg(Ah + fb0 + (ktb + d) * 256);
            rl[0][d] = __ldcg(Al + fb0 + (ktb + d) * 256);
            rh[1][d] = __ldcg(Ah + fb1 + (ktb + d) * 256);
            rl[1][d] = __ldcg(Al + fb1 + (ktb + d) * 256);
        }

        #pragma unroll 1
        for (int k2 = 0; k2 < 16; k2++) {
            const int cur = k2 & 1;
            const uint4* wrow = Wfrag + (ktb + k2) * 128 + lane;
            uint4 wf0 = wrow[0];
            uint4 wf1 = wrow[32];
            uint4 wf2 = wrow[64];
            uint4 wf3 = wrow[96];
            #pragma unroll
            for (int i = 0; i < 2; i++) {
                uint4 ah = rh[i][cur], al = rl[i][cur];
                if (k2 < 14) {
                    int fb = i ? fb1 : fb0;
                    rh[i][cur] = __ldcg(Ah + fb + (ktb + k2 + 2) * 256);
                    rl[i][cur] = __ldcg(Al + fb + (ktb + k2 + 2) * 256);
                }
                mma_bf16(acc[i][0], ah, wf0.x, wf0.y);
                mma_bf16(acc[i][1], ah, wf1.x, wf1.y);
                mma_bf16(acc[i][2], ah, wf2.x, wf2.y);
                mma_bf16(acc[i][3], ah, wf3.x, wf3.y);
                mma_bf16(acc[i][0], al, wf0.x, wf0.y);
                mma_bf16(acc[i][1], al, wf1.x, wf1.y);
                mma_bf16(acc[i][2], al, wf2.x, wf2.y);
                mma_bf16(acc[i][3], al, wf3.x, wf3.y);
                mma_bf16(acc[i][0], ah, wf0.z, wf0.w);
                mma_bf16(acc[i][1], ah, wf1.z, wf1.w);
                mma_bf16(acc[i][2], ah, wf2.z, wf2.w);
                mma_bf16(acc[i][3], ah, wf3.z, wf3.w);
            }
        }

        // ---- load elementwise operands (ring regs now dead) --------------------
        float Gr[4], Pr[4], xnv, hnv;
        {
            size_t gb = ((size_t)t * BB + b) * G4 + n0 + jj;
            #pragma unroll
            for (int q = 0; q < 4; q++) {
                Gr[q] = __ldg(&g_G[gb + q * HH]);
                Pr[q] = EPSF * __ldg(&gp[gb + q * HH]);
            }
            xnv = __ldg(&g_xn2[t * BB + b]);
            hnv = __ldcg(&g_hn2[t * BB + b]);
        }

        // ---- dump partial D to pre[kq] ------------------------------------------
        {
            float* ph = pre + kq * PRE_Q;
            #pragma unroll
            for (int i = 0; i < 2; i++) {
                int r0 = (2 * mtp + i) * 16 + gid;
                #pragma unroll
                for (int q = 0; q < 4; q++) {
                    float2 v0; v0.x = acc[i][q][0]; v0.y = acc[i][q][1];
                    float2 v1; v1.x = acc[i][q][2]; v1.y = acc[i][q][3];
                    *(float2*)&ph[r0 * PRE_STRIDE + q * 8 + 2 * tig]       = v0;
                    *(float2*)&ph[(r0 + 8) * PRE_STRIDE + q * 8 + 2 * tig] = v1;
                }
            }
        }
        __syncthreads();

        // ---- fused LSTM + MAGE elementwise (1 item/thread) ----------------------
        uint4* AhN = g_Ahi[(t + 1) & 1];
        uint4* AlN = g_Alo[(t + 1) & 1];
        u16* AhN16 = (u16*)AhN;
        u16* AlN16 = (u16*)AlN;

        const int c    = n0 + jj;
        const int ktc  = c >> 4;
        const int ci   = c & 15;
        const int half = ci & 1;
        const int tigc = (ci & 7) >> 1;
        const int regc = ((ci >> 3) & 1) << 1;

        float h2, dh2;
        size_t ob;
        {
            float ph[4], th[4];
            #pragma unroll
            for (int q = 0; q < 4; q++) {
                float sp = 0.f, st_ = 0.f;
                #pragma unroll
                for (int qt = 0; qt < 4; qt++) {
                    sp  += pre[qt * PRE_Q + b * PRE_STRIDE + q * 8 + jj];
                    st_ += pre[qt * PRE_Q + (64 + b) * PRE_STRIDE + q * 8 + jj];
                }
                ph[q] = sp; th[q] = st_;
            }

            float pi = ph[0] + Gr[0];
            float pf = ph[1] + Gr[1];
            float pg = ph[2] + Gr[2];
            float po = ph[3] + Gr[3];

            float n2  = xnv + hnv + 2.0f;
            float nrm = sqrtf(n2);
            float inv = 1.0f / nrm;
            float s   = (n2 - 2.0f) * inv;

            float iv = 1.0f / (1.0f + __expf(-pi));
            float fv = 1.0f / (1.0f + __expf(-pf));
            float gv = __tanhf(pg);
            float ov = 1.0f / (1.0f + __expf(-po));

            float g0 = Pr[0], g1 = Pr[1], g2 = Pr[2], g3 = Pr[3];
            float dpi = g0 * (s + inv) + g1 * inv + th[0];
            float dpf = g1 * s + (g2 + g3) * inv + th[1];
            float dpg = g2 * s + (g0 + g1) * inv + th[2];
            float dpo = g3 * s + (g2 + g3) * inv + th[3];

            float di  = iv * (1.f - iv) * dpi;
            float df  = fv * (1.f - fv) * dpf;
            float dg  = (1.f - gv * gv) * dpg;
            float dov = ov * (1.f - ov) * dpo;

            float c2  = fv * cst + iv * gv;
            float dc2 = df * cst + fv * dcst + di * gv + iv * dg;
            float tc  = __tanhf(c2);
            h2  = ov * tc;
            dh2 = dov * tc + ov * (1.f - tc * tc) * dc2;
            cst = c2; dcst = dc2;

            ob = ((size_t)t * BB + b) * HH + c;

            // scatter into next-step fragment image: h row b, dh row b+64
            {
                int r = b;
                int mtr = r >> 4, ri = r & 15;
                int lane_f = (ri & 7) * 4 + tigc;
                int reg = (ri >> 3) + regc;
                size_t si = ((size_t)(ktc * 8 + mtr) * 32 + lane_f) * 8 + reg * 2 + half;
                u16 hh, hl;
                split_bf(h2, hh, hl);
                AhN16[si] = hh;
                AlN16[si] = hl;
            }
            {
                int r = b + 64;
                int mtr = r >> 4, ri = r & 15;
                int lane_f = (ri & 7) * 4 + tigc;
                int reg = (ri >> 3) + regc;
                size_t si = ((size_t)(ktc * 8 + mtr) * 32 + lane_f) * 8 + reg * 2 + half;
                u16 hh, hl;
                split_bf(dh2, hh, hl);
                AhN16[si] = hh;
                AlN16[si] = hl;
            }

            float sum = h2 * h2;
            #pragma unroll
            for (int o = 1; o < 8; o <<= 1)
                sum += __shfl_xor_sync(0xffffffffu, sum, o);
            if (jj == 0) atomicAdd(&g_hn2[(t + 1) * BB + b], sum);
        }

        // ---- barrier: arrive early, overlap out[] stores with the poll ---------
        __threadfence();
        __syncthreads();
        if (tid == 0) atomicAdd(&g_bar, 1u);
        out[ob]       = h2;
        out[OFF + ob] = dh2;
        if (tid == 0) {
            unsigned tgt = (unsigned)(t + 1) * NCTA;
            unsigned v;
            do {
                asm volatile("ld.acquire.gpu.b32 %0, [%1];"
                             : "=r"(v) : "l"(&g_bar) : "memory");
            } while (v < tgt);
        }
        __syncthreads();
    }
}

// ---------------- launch ------------------------------------------------------
extern "C" void kernel_launch(void* const* d_in, const int* in_sizes, int n_in,
                              void* d_out, int out_size) {
    const float* x   = (const float*)d_in[0];   // [T,B,D]
    const float* g   = (const float*)d_in[1];   // [T,B,4H]
    const float* Wih = (const float*)d_in[2];   // [4H,D]
    const float* Whh = (const float*)d_in[3];   // [4H,H]
    const float* bih = (const float*)d_in[4];   // [4H]
    const float* bhh = (const float*)d_in[5];   // [4H]
    float* out = (float*)d_out;                 // [2,T,B,H]

    cudaFuncSetAttribute(persist_kernel, cudaFuncAttributeMaxDynamicSharedMemorySize,
                         SMEM_TOTAL);
    cudaFuncSetAttribute(pre_gemm_hmma, cudaFuncAttributeMaxDynamicSharedMemorySize,
                         PG_SMEM);

    init_kernel<<<256, 256>>>();
    xnorm_kernel<<<TT * BB, 256>>>(x);
    prepack_x<<<TT * BB, 256>>>(x);
    prepack_w<<<G4, 256>>>(Wih);
    pre_gemm_hmma<<<dim3(32, 128), 256, PG_SMEM>>>(bih, bhh);
    persist_kernel<<<NCTA, NTHR, SMEM_TOTAL>>>(g, Whh, out);
}

// round 16
// speedup vs baseline: 1.6695x; 1.6695x over previous
#include <cuda_runtime.h>
#include <cuda_bf16.h>
#include <cuda_fp16.h>
#include <cstdint>

#define TT 256
#define BB 64
#define DD 1024
#define HH 1024
#define G4 4096
#define EPSF 0.01f
#define NCTA 128
#define NTHR 512

typedef unsigned long long ull;
typedef unsigned short u16;

// ---------------- device scratch -------------------------------------------
static __device__ float g_G[(size_t)TT * BB * G4];   // x@W_ih.T + b_ih + b_hh
static __device__ float g_xn2[TT * BB];              // |x_t|^2
static __device__ float g_hn2[(TT + 1) * BB];        // |h_t|^2 (atomics)
// A-image in mma fragment layout, SINGLE fp16 plane:
// [parity][kt(64)*mt(8)*lane(32)] uint4
static __device__ uint4 g_Afp[2][16384];
// packed fragment images for pre_gemm (bf16 hi/lo, SMEM-layout-identical)
static __device__ uint4 g_xpack[(size_t)128 * 64 * 512];  // [mb][kt][mt][lane][2]
static __device__ uint4 g_wpack[(size_t)32 * 64 * 512];   // [nb][kt][wq][lane]
static __device__ unsigned g_bar;                    // global step barrier

// ---------------- init (runs every replay) ----------------------------------
__global__ void init_kernel() {
    int idx = blockIdx.x * blockDim.x + threadIdx.x;
    int stride = gridDim.x * blockDim.x;
    uint4 z = make_uint4(0u, 0u, 0u, 0u);
    for (int i = idx; i < 16384; i += stride) g_Afp[0][i] = z;
    for (int i = idx; i < (TT + 1) * BB; i += stride) g_hn2[i] = 0.f;
    if (idx == 0) g_bar = 0u;
}

// ---------------- |x_t|^2 ---------------------------------------------------
__global__ void xnorm_kernel(const float* __restrict__ x) {
    int row = blockIdx.x;
    const float* xr = x + (size_t)row * DD;
    float s = 0.f;
    for (int i = threadIdx.x; i < DD; i += blockDim.x) { float v = xr[i]; s += v * v; }
    __shared__ float red[8];
    #pragma unroll
    for (int o = 16; o > 0; o >>= 1) s += __shfl_xor_sync(0xffffffffu, s, o);
    if ((threadIdx.x & 31) == 0) red[threadIdx.x >> 5] = s;
    __syncthreads();
    if (threadIdx.x < 8) {
        s = red[threadIdx.x];
        #pragma unroll
        for (int o = 4; o > 0; o >>= 1) s += __shfl_xor_sync(0xffu, s, o);
        if (threadIdx.x == 0) g_xn2[row] = s;
    }
}

// ---------------- helpers -----------------------------------------------------
__device__ __forceinline__ void mma_bf16(float* d, uint4 a, uint32_t b0, uint32_t b1) {
    asm volatile(
        "mma.sync.aligned.m16n8k16.row.col.f32.bf16.bf16.f32 "
        "{%0,%1,%2,%3}, {%4,%5,%6,%7}, {%8,%9}, {%0,%1,%2,%3};"
        : "+f"(d[0]), "+f"(d[1]), "+f"(d[2]), "+f"(d[3])
        : "r"(a.x), "r"(a.y), "r"(a.z), "r"(a.w), "r"(b0), "r"(b1));
}
__device__ __forceinline__ void mma_f16(float* d, uint4 a, uint32_t b0, uint32_t b1) {
    asm volatile(
        "mma.sync.aligned.m16n8k16.row.col.f32.f16.f16.f32 "
        "{%0,%1,%2,%3}, {%4,%5,%6,%7}, {%8,%9}, {%0,%1,%2,%3};"
        : "+f"(d[0]), "+f"(d[1]), "+f"(d[2]), "+f"(d[3])
        : "r"(a.x), "r"(a.y), "r"(a.z), "r"(a.w), "r"(b0), "r"(b1));
}
__device__ __forceinline__ u16 bfu(__nv_bfloat16 b) {
    return __bfloat16_as_ushort(b);
}
__device__ __forceinline__ void split_bf(float v, u16& h, u16& l) {
    __nv_bfloat16 hb = __float2bfloat16(v);
    h = bfu(hb);
    l = bfu(__float2bfloat16(v - __bfloat162float(hb)));
}
__device__ __forceinline__ void split_h16(float v, u16& h, u16& l) {
    __half hb = __float2half_rn(v);
    h = __half_as_ushort(hb);
    l = __half_as_ushort(__float2half_rn(v - __half2float(hb)));
}

// ---------------- prepack: x -> fragment image (bf16 hi/lo) -------------------
__global__ void prepack_x(const float* __restrict__ x) {
    const int row = blockIdx.x;          // 0..16383
    const int kq  = threadIdx.x;         // float4 index 0..255
    float4 v = __ldg((const float4*)(x + (size_t)row * DD) + kq);
    const int mb = row >> 7, r = row & 127, mt = r >> 4;
    u16* dst = (u16*)g_xpack;
    #pragma unroll
    for (int p = 0; p < 2; p++) {
        int kp = kq * 2 + p;
        int kt = kp >> 3, tigc = kp & 3, regk = (kp >> 2) & 1;
        int lane_f = (r & 7) * 4 + tigc;
        int reg = ((r >> 3) & 1) + 2 * regk;
        float v0 = p ? v.z : v.x, v1 = p ? v.w : v.y;
        u16 h0, l0, h1, l1;
        split_bf(v0, h0, l0); split_bf(v1, h1, l1);
        size_t base = ((((size_t)mb * 64 + kt) * 8 + mt) * 32 + lane_f) * 16 + reg * 2;
        *(ushort2*)&dst[base]     = make_ushort2(h0, h1);
        *(ushort2*)&dst[base + 8] = make_ushort2(l0, l1);
    }
}

// ---------------- prepack: W_ih -> fragment image (bf16 hi/lo) ----------------
__global__ void prepack_w(const float* __restrict__ Wih) {
    const int row = blockIdx.x;          // n-row 0..4095
    const int kq  = threadIdx.x;
    float4 v = __ldg((const float4*)(Wih + (size_t)row * DD) + kq);
    const int nb = row >> 7, r = row & 127, wq = r >> 3;
    u16* dst = (u16*)g_wpack;
    #pragma unroll
    for (int p = 0; p < 2; p++) {
        int kp = kq * 2 + p;
        int kt = kp >> 3, tigc = kp & 3, regk = (kp >> 2) & 1;
        int lane_f = (r & 7) * 4 + tigc;
        float v0 = p ? v.z : v.x, v1 = p ? v.w : v.y;
        u16 h0, l0, h1, l1;
        split_bf(v0, h0, l0); split_bf(v1, h1, l1);
        size_t base = ((((size_t)nb * 64 + kt) * 16 + wq) * 32 + lane_f) * 8 + regk * 2;
        *(ushort2*)&dst[base]     = make_ushort2(h0, h1);
        *(ushort2*)&dst[base + 4] = make_ushort2(l0, l1);
    }
}

// ---------------- HMMA precompute GEMM: G = x @ W_ih.T + (b_ih + b_hh) ------
#define PG_SMEM (4096 * 16)

__global__ void __launch_bounds__(256)
pre_gemm_hmma(const float* __restrict__ bih, const float* __restrict__ bhh) {
    extern __shared__ __align__(16) uint4 sv[];
    uint4* xv = sv;          // [buf][1024]
    uint4* wv = sv + 2048;   // [buf][1024]

    const int tid  = threadIdx.x;
    const int w    = tid >> 5;
    const int lane = tid & 31;
    const int gid  = lane >> 2;
    const int tig  = lane & 3;
    const int wm   = w >> 1;
    const int wn   = w & 1;
    const int nb   = blockIdx.x;
    const int mb   = blockIdx.y;
    const int n0   = nb * 128;
    const int m0   = mb * 128;

    const uint4* xg = g_xpack + (size_t)mb * 64 * 512;
    const uint4* wg = g_wpack + (size_t)nb * 64 * 512;

    float acc[2][8][4];
    #pragma unroll
    for (int i = 0; i < 2; i++)
        #pragma unroll
        for (int j = 0; j < 8; j++)
            #pragma unroll
            for (int e = 0; e < 4; e++) acc[i][j][e] = 0.f;

    uint4 st[8];
    auto LDGC = [&](int ch) {
        const uint4* xs = xg + (size_t)ch * 1024;
        const uint4* ws = wg + (size_t)ch * 1024;
        #pragma unroll
        for (int i = 0; i < 4; i++) st[i]     = __ldg(xs + tid + i * 256);
        #pragma unroll
        for (int i = 0; i < 4; i++) st[4 + i] = __ldg(ws + tid + i * 256);
    };
    auto STSC = [&](int buf) {
        #pragma unroll
        for (int i = 0; i < 4; i++) xv[buf * 1024 + tid + i * 256] = st[i];
        #pragma unroll
        for (int i = 0; i < 4; i++) wv[buf * 1024 + tid + i * 256] = st[4 + i];
    };

    LDGC(0);
    STSC(0);
    __syncthreads();

    for (int ch = 0; ch < 32; ch++) {
        const int buf = ch & 1;
        if (ch < 31) LDGC(ch + 1);
        #pragma unroll
        for (int kt = 0; kt < 2; kt++) {
            int fi0 = buf * 1024 + ((kt * 8 + wm * 2) * 32 + lane) * 2;
            uint4 ah0 = xv[fi0],      al0 = xv[fi0 + 1];
            uint4 ah1 = xv[fi0 + 64], al1 = xv[fi0 + 65];
            #pragma unroll
            for (int nf = 0; nf < 8; nf++) {
                uint4 wvv = wv[buf * 1024 + (kt * 16 + wn * 8 + nf) * 32 + lane];
                mma_bf16(acc[0][nf], ah0, wvv.x, wvv.y);
                mma_bf16(acc[0][nf], al0, wvv.x, wvv.y);
                mma_bf16(acc[0][nf], ah0, wvv.z, wvv.w);
                mma_bf16(acc[1][nf], ah1, wvv.x, wvv.y);
                mma_bf16(acc[1][nf], al1, wvv.x, wvv.y);
                mma_bf16(acc[1][nf], ah1, wvv.z, wvv.w);
            }
        }
        if (ch < 31) {
            STSC(buf ^ 1);
            __syncthreads();
        }
    }

    #pragma unroll
    for (int nf = 0; nf < 8; nf++) {
        int col = n0 + wn * 64 + nf * 8 + tig * 2;
        float bs0 = __ldg(&bih[col])     + __ldg(&bhh[col]);
        float bs1 = __ldg(&bih[col + 1]) + __ldg(&bhh[col + 1]);
        #pragma unroll
        for (int im = 0; im < 2; im++) {
            int row = m0 + wm * 32 + im * 16 + gid;
            float2 v0; v0.x = acc[im][nf][0] + bs0; v0.y = acc[im][nf][1] + bs1;
            float2 v1; v1.x = acc[im][nf][2] + bs0; v1.y = acc[im][nf][3] + bs1;
            *(float2*)&g_G[(size_t)row * G4 + col]       = v0;
            *(float2*)&g_G[(size_t)(row + 8) * G4 + col] = v1;
        }
    }
}

// ---------------- persistent HMMA recurrence kernel ---------------------------
// R14 structure; fp16 2-pass: A single fp16 plane (RN), W fp16 hi/lo.
// 16 warps; warp = (mt = w&7, kh = w>>3). Depth-4 A ring (hi plane only).
// SMEM: Wfrag uint4[64 kt][4 q][32 lane] = 128KB; pre float[2 kh][128][34].
#define WFRAG_BYTES (256 * 32 * 16)
#define PRE_STRIDE 34
#define PRE_HALF   (128 * PRE_STRIDE)
#define SMEM_TOTAL (WFRAG_BYTES + 2 * PRE_HALF * 4)

__global__ void __launch_bounds__(NTHR, 1)
persist_kernel(const float* __restrict__ gp, const float* __restrict__ Whh,
               float* __restrict__ out) {
    extern __shared__ __align__(16) char sraw[];
    uint4* Wfrag = (uint4*)sraw;
    float* pre   = (float*)(sraw + WFRAG_BYTES);

    const int tid  = threadIdx.x;
    const int w    = tid >> 5;
    const int lane = tid & 31;
    const int mt   = w & 7;
    const int kh   = w >> 3;
    const int gid  = lane >> 2;
    const int tig  = lane & 3;
    const int n0   = blockIdx.x * 8;
    const int jj   = tid & 7;
    const int b    = tid >> 3;           // 0..63 (tid < 512)

    // ---- one-time: build W fragments (fp16 hi/lo) into SMEM -----------------
    #pragma unroll 1
    for (int idx = w; idx < 256; idx += 16) {
        int q = idx & 3, kt = idx >> 2;
        const float* wr = Whh + (size_t)(q * HH + n0 + gid) * HH + kt * 16 + tig * 2;
        float v00 = __ldg(wr), v01 = __ldg(wr + 1);
        float v10 = __ldg(wr + 8), v11 = __ldg(wr + 9);
        u16 h00, l00, h01, l01, h10, l10, h11, l11;
        split_h16(v00, h00, l00); split_h16(v01, h01, l01);
        split_h16(v10, h10, l10); split_h16(v11, h11, l11);
        Wfrag[idx * 32 + lane] = make_uint4(
            (uint32_t)h00 | ((uint32_t)h01 << 16),
            (uint32_t)h10 | ((uint32_t)h11 << 16),
            (uint32_t)l00 | ((uint32_t)l01 << 16),
            (uint32_t)l10 | ((uint32_t)l11 << 16));
    }
    __syncthreads();

    float cst = 0.f, dcst = 0.f;
    const size_t OFF = (size_t)TT * BB * HH;

    for (int t = 0; t < TT; t++) {
        // ---- prefetch elementwise operands ----------------------------------
        float Gr[4], Pr[4], xnv, hnv;
        {
            size_t gb = ((size_t)t * BB + b) * G4 + n0 + jj;
            #pragma unroll
            for (int q = 0; q < 4; q++) {
                Gr[q] = __ldg(&g_G[gb + q * HH]);
                Pr[q] = EPSF * __ldg(&gp[gb + q * HH]);
            }
            xnv = __ldg(&g_xn2[t * BB + b]);
            hnv = __ldcg(&g_hn2[t * BB + b]);
        }

        // ---- HMMA mainloop: 2-pass fp16, depth-4 A register ring -------------
        float acc[4][4];
        #pragma unroll
        for (int q = 0; q < 4; q++)
            #pragma unroll
            for (int e = 0; e < 4; e++) acc[q][e] = 0.f;

        const uint4* Af = g_Afp[t & 1];
        const int ktb   = kh * 32;
        const int fbase = mt * 32 + lane;

        uint4 rh[4];
        #pragma unroll
        for (int d = 0; d < 4; d++)
            rh[d] = __ldcg(Af + fbase + (ktb + d) * 256);

        #pragma unroll 1
        for (int ko = 0; ko < 32; ko += 4) {
            #pragma unroll
            for (int u = 0; u < 4; u++) {
                const int k2 = ko + u;
                uint4 ah = rh[u];
                if (k2 < 28)
                    rh[u] = __ldcg(Af + fbase + (ktb + k2 + 4) * 256);
                const uint4* wrow = Wfrag + (ktb + k2) * 128 + lane;
                uint4 wf0 = wrow[0];
                uint4 wf1 = wrow[32];
                uint4 wf2 = wrow[64];
                uint4 wf3 = wrow[96];
                // pass 1: A * Whi (4 independent chains)
                mma_f16(acc[0], ah, wf0.x, wf0.y);
                mma_f16(acc[1], ah, wf1.x, wf1.y);
                mma_f16(acc[2], ah, wf2.x, wf2.y);
                mma_f16(acc[3], ah, wf3.x, wf3.y);
                // pass 2: A * Wlo
                mma_f16(acc[0], ah, wf0.z, wf0.w);
                mma_f16(acc[1], ah, wf1.z, wf1.w);
                mma_f16(acc[2], ah, wf2.z, wf2.w);
                mma_f16(acc[3], ah, wf3.z, wf3.w);
            }
        }

        // ---- dump partial D to pre[kh] ----------------------------------------
        {
            float* ph = pre + kh * PRE_HALF;
            int r0 = mt * 16 + gid;
            #pragma unroll
            for (int q = 0; q < 4; q++) {
                float2 v0; v0.x = acc[q][0]; v0.y = acc[q][1];
                float2 v1; v1.x = acc[q][2]; v1.y = acc[q][3];
                *(float2*)&ph[r0 * PRE_STRIDE + q * 8 + 2 * tig]       = v0;
                *(float2*)&ph[(r0 + 8) * PRE_STRIDE + q * 8 + 2 * tig] = v1;
            }
        }
        __syncthreads();

        // ---- fused LSTM + MAGE elementwise (1 item/thread) --------------------
        u16* AN16 = (u16*)g_Afp[(t + 1) & 1];

        const int c    = n0 + jj;
        const int ktc  = c >> 4;
        const int ci   = c & 15;
        const int half = ci & 1;
        const int tigc = (ci & 7) >> 1;
        const int regc = ((ci >> 3) & 1) << 1;

        float h2, dh2;
        size_t ob;
        {
            float ph[4], th[4];
            #pragma unroll
            for (int q = 0; q < 4; q++) {
                ph[q] = pre[b * PRE_STRIDE + q * 8 + jj]
                      + pre[PRE_HALF + b * PRE_STRIDE + q * 8 + jj];
                th[q] = pre[(64 + b) * PRE_STRIDE + q * 8 + jj]
                      + pre[PRE_HALF + (64 + b) * PRE_STRIDE + q * 8 + jj];
            }

            float pi = ph[0] + Gr[0];
            float pf = ph[1] + Gr[1];
            float pg = ph[2] + Gr[2];
            float po = ph[3] + Gr[3];

            float n2  = xnv + hnv + 2.0f;
            float nrm = sqrtf(n2);
            float inv = 1.0f / nrm;
            float s   = (n2 - 2.0f) * inv;

            float iv = 1.0f / (1.0f + __expf(-pi));
            float fv = 1.0f / (1.0f + __expf(-pf));
            float gv = __tanhf(pg);
            float ov = 1.0f / (1.0f + __expf(-po));

            float g0 = Pr[0], g1 = Pr[1], g2 = Pr[2], g3 = Pr[3];
            float dpi = g0 * (s + inv) + g1 * inv + th[0];
            float dpf = g1 * s + (g2 + g3) * inv + th[1];
            float dpg = g2 * s + (g0 + g1) * inv + th[2];
            float dpo = g3 * s + (g2 + g3) * inv + th[3];

            float di  = iv * (1.f - iv) * dpi;
            float df  = fv * (1.f - fv) * dpf;
            float dg  = (1.f - gv * gv) * dpg;
            float dov = ov * (1.f - ov) * dpo;

            float c2  = fv * cst + iv * gv;
            float dc2 = df * cst + fv * dcst + di * gv + iv * dg;
            float tc  = __tanhf(c2);
            h2  = ov * tc;
            dh2 = dov * tc + ov * (1.f - tc * tc) * dc2;
            cst = c2; dcst = dc2;

            ob = ((size_t)t * BB + b) * HH + c;

            // scatter into next-step fragment image (single fp16 plane):
            // h at row b, dh at row b+64
            {
                int r = b;
                int mtr = r >> 4, ri = r & 15;
                int lane_f = (ri & 7) * 4 + tigc;
                int reg = (ri >> 3) + regc;
                size_t si = ((size_t)(ktc * 8 + mtr) * 32 + lane_f) * 8 + reg * 2 + half;
                AN16[si] = __half_as_ushort(__float2half_rn(h2));
            }
            {
                int r = b + 64;
                int mtr = r >> 4, ri = r & 15;
                int lane_f = (ri & 7) * 4 + tigc;
                int reg = (ri >> 3) + regc;
                size_t si = ((size_t)(ktc * 8 + mtr) * 32 + lane_f) * 8 + reg * 2 + half;
                AN16[si] = __half_as_ushort(__float2half_rn(dh2));
            }

            float sum = h2 * h2;
            #pragma unroll
            for (int o = 1; o < 8; o <<= 1)
                sum += __shfl_xor_sync(0xffffffffu, sum, o);
            if (jj == 0) atomicAdd(&g_hn2[(t + 1) * BB + b], sum);
        }

        // ---- barrier: arrive early, overlap out[] stores with the poll ---------
        __threadfence();
        __syncthreads();
        if (tid == 0) atomicAdd(&g_bar, 1u);
        out[ob]       = h2;
        out[OFF + ob] = dh2;
        if (tid == 0) {
            unsigned tgt = (unsigned)(t + 1) * NCTA;
            unsigned v;
            do {
                asm volatile("ld.acquire.gpu.b32 %0, [%1];"
                             : "=r"(v) : "l"(&g_bar) : "memory");
            } while (v < tgt);
        }
        __syncthreads();
    }
}

// ---------------- launch ------------------------------------------------------
extern "C" void kernel_launch(void* const* d_in, const int* in_sizes, int n_in,
                              void* d_out, int out_size) {
    const float* x   = (const float*)d_in[0];   // [T,B,D]
    const float* g   = (const float*)d_in[1];   // [T,B,4H]
    const float* Wih = (const float*)d_in[2];   // [4H,D]
    const float* Whh = (const float*)d_in[3];   // [4H,H]
    const float* bih = (const float*)d_in[4];   // [4H]
    const float* bhh = (const float*)d_in[5];   // [4H]
    float* out = (float*)d_out;                 // [2,T,B,H]

    cudaFuncSetAttribute(persist_kernel, cudaFuncAttributeMaxDynamicSharedMemorySize,
                         SMEM_TOTAL);
    cudaFuncSetAttribute(pre_gemm_hmma, cudaFuncAttributeMaxDynamicSharedMemorySize,
                         PG_SMEM);

    init_kernel<<<256, 256>>>();
    xnorm_kernel<<<TT * BB, 256>>>(x);
    prepack_x<<<TT * BB, 256>>>(x);
    prepack_w<<<G4, 256>>>(Wih);
    pre_gemm_hmma<<<dim3(32, 128), 256, PG_SMEM>>>(bih, bhh);
    persist_kernel<<<NCTA, NTHR, SMEM_TOTAL>>>(g, Whh, out);
}